// round 10
// baseline (speedup 1.0000x reference)
#include <cuda_runtime.h>
#include <cuda_bf16.h>
#include <math.h>

#define Bsz 64
#define T 512
#define D 512
#define H 512
#define NG 2048  // 4*H
#define MTOT (Bsz*T)  // 32768

typedef unsigned long long u64;
typedef unsigned int u32;
typedef unsigned short u16;

// ---- common helpers ----
__device__ __forceinline__ u32 smem_u32(const void* p) {
    u32 a;
    asm("{ .reg .u64 t; cvta.to.shared.u64 t, %1; cvt.u32.u64 %0, t; }" : "=r"(a) : "l"(p));
    return a;
}
__device__ __forceinline__ void ldm4(u32* r, u32 p) {
    asm volatile("ldmatrix.sync.aligned.m8n8.x4.shared.b16 {%0,%1,%2,%3}, [%4];"
        : "=r"(r[0]), "=r"(r[1]), "=r"(r[2]), "=r"(r[3]) : "r"(p));
}
__device__ __forceinline__ void mma_bf16(float* d, const u32* a, u32 b0, u32 b1) {
    asm volatile("mma.sync.aligned.m16n8k16.row.col.f32.bf16.bf16.f32 "
        "{%0,%1,%2,%3}, {%4,%5,%6,%7}, {%8,%9}, {%0,%1,%2,%3};"
        : "+f"(d[0]), "+f"(d[1]), "+f"(d[2]), "+f"(d[3])
        : "r"(a[0]), "r"(a[1]), "r"(a[2]), "r"(a[3]), "r"(b0), "r"(b1));
}
__device__ __forceinline__ void split_bf16(float x, u16& hb, u16& lb) {
    __nv_bfloat16 h = __float2bfloat16_rn(x);
    hb = __bfloat16_as_ushort(h);
    lb = __bfloat16_as_ushort(__float2bfloat16_rn(x - __bfloat162float(h)));
}
__device__ __forceinline__ float sigf(float x) {
    float e, r;
    asm("ex2.approx.f32 %0, %1;" : "=f"(e) : "f"(-x * 1.4426950408889634f));
    asm("rcp.approx.f32 %0, %1;" : "=f"(r) : "f"(1.0f + e));
    return r;
}
__device__ __forceinline__ float tanh_fast(float x) {
    return fmaf(2.f, sigf(2.f * x), -1.f);
}
__device__ __forceinline__ void red_release_add(unsigned* p, unsigned v) {
    asm volatile("red.release.gpu.global.add.u32 [%0], %1;" :: "l"(p), "r"(v) : "memory");
}
__device__ __forceinline__ unsigned ld_acquire(const unsigned* p) {
    unsigned v;
    asm volatile("ld.acquire.gpu.global.u32 %0, [%1];" : "=r"(v) : "l"(p) : "memory");
    return v;
}
#define CP16(dst, src) \
    asm volatile("cp.async.cg.shared.global [%0], [%1], 16;" :: "r"(dst), "l"(src))
#define CP_COMMIT asm volatile("cp.async.commit_group;")
#define CP_WAIT0 asm volatile("cp.async.wait_group 0;")
#define BAR_SYNC(id, cnt) asm volatile("bar.sync %0, %1;" :: "r"(id), "r"(cnt) : "memory")

// ---- scratch ----
__device__ float g_ZF[(size_t)T * Bsz * NG];
__device__ float g_ZB[(size_t)T * Bsz * NG];
__device__ __align__(16) __nv_bfloat16 g_hh[2][2][Bsz * H];
__device__ __align__(16) __nv_bfloat16 g_hl[2][2][Bsz * H];
__device__ __align__(16) __nv_bfloat16 g_xh[(size_t)MTOT * D];   // row m = t*B + b
__device__ __align__(16) __nv_bfloat16 g_xl[(size_t)MTOT * D];
__device__ __align__(16) __nv_bfloat16 g_wth[2][(size_t)NG * 1024]; // [dir][n][k]
__device__ __align__(16) __nv_bfloat16 g_wtl[2][(size_t)NG * 1024];
__device__ __align__(256) unsigned g_flag[2][2][64];

__global__ void init_kernel() {
    int i = blockIdx.x * blockDim.x + threadIdx.x;
    if (i < Bsz * H) {
        __nv_bfloat16 z = __float2bfloat16(0.f);
        g_hh[0][0][i] = z; g_hh[0][1][i] = z; g_hh[1][0][i] = z; g_hh[1][1][i] = z;
        g_hl[0][0][i] = z; g_hl[0][1][i] = z; g_hl[1][0][i] = z; g_hl[1][1][i] = z;
    }
    if (i < 256) ((unsigned*)g_flag)[i] = 0u;
}

__global__ void __launch_bounds__(256) split_x_kernel(const float* __restrict__ x) {
    int id = blockIdx.x * 256 + threadIdx.x;
    int m = id >> 6, c8 = id & 63;
    int b = m & (Bsz - 1), t = m >> 6;
    const float4* xp = (const float4*)(x + ((size_t)b * T + t) * D + c8 * 8);
    float4 v0 = xp[0], v1 = xp[1];
    u16 h[8], l[8];
    split_bf16(v0.x, h[0], l[0]); split_bf16(v0.y, h[1], l[1]);
    split_bf16(v0.z, h[2], l[2]); split_bf16(v0.w, h[3], l[3]);
    split_bf16(v1.x, h[4], l[4]); split_bf16(v1.y, h[5], l[5]);
    split_bf16(v1.z, h[6], l[6]); split_bf16(v1.w, h[7], l[7]);
    uint4 ph, pl;
    ph.x = (u32)h[0] | ((u32)h[1] << 16); ph.y = (u32)h[2] | ((u32)h[3] << 16);
    ph.z = (u32)h[4] | ((u32)h[5] << 16); ph.w = (u32)h[6] | ((u32)h[7] << 16);
    pl.x = (u32)l[0] | ((u32)l[1] << 16); pl.y = (u32)l[2] | ((u32)l[3] << 16);
    pl.z = (u32)l[4] | ((u32)l[5] << 16); pl.w = (u32)l[6] | ((u32)l[7] << 16);
    *(uint4*)(g_xh + (size_t)m * D + c8 * 8) = ph;
    *(uint4*)(g_xl + (size_t)m * D + c8 * 8) = pl;
}

__global__ void __launch_bounds__(256) split_w_kernel(
    const float* __restrict__ Wfw, const float* __restrict__ Wbw) {
    __shared__ float tile[32][33];
    int dir = blockIdx.z;
    int k0 = blockIdx.x * 32, n0 = blockIdx.y * 32;
    const float* W = dir ? Wbw : Wfw;
    int tid = threadIdx.x;
#pragma unroll
    for (int i = 0; i < 4; i++) {
        int idx = tid + i * 256;
        int r = idx >> 5, c = idx & 31;
        tile[r][c] = W[(size_t)(k0 + r) * NG + n0 + c];
    }
    __syncthreads();
#pragma unroll
    for (int i = 0; i < 4; i++) {
        int idx = tid + i * 256;
        int r = idx >> 5, c = idx & 31;
        u16 hb, lb; split_bf16(tile[c][r], hb, lb);
        size_t o = (size_t)(n0 + r) * 1024 + k0 + c;
        g_wth[dir][o] = __ushort_as_bfloat16(hb);
        g_wtl[dir][o] = __ushort_as_bfloat16(lb);
    }
}

// ---------------------------------------------------------------------------
// Fused persistent kernel: 128 blocks x 384 threads.
// Warps 0-7: recurrent LSTM consumers (as round 9).
// Warps 8-11: Z producers — compute this block's own Z slice (32 rows x
// 64 gate-cols) per t, in consumption order, write st.cg + bump smem counter.
// ---------------------------------------------------------------------------
#define A_OFF2 0
#define B_OFF2 65536
#define SP_OFF2 (B_OFF2 + 131072)      // 196608, 2KB P handoff
#define PA_OFF  (SP_OFF2 + 2048)       // 198656: x chunk hi 4KB | lo 4KB
#define PB_OFF  (PA_OFF + 8192)        // 206848: Wx chunk hi 8KB | lo 8KB
#define PCNT_OFF (PB_OFF + 16384)      // 223232
#define P2_SMEM  (PCNT_OFF + 128)      // 223360

__global__ void __launch_bounds__(384, 1) lstm_persistent(
    float* __restrict__ out,
    const float* __restrict__ bfw, const float* __restrict__ bbw)
{
    extern __shared__ char smem[];
    const u32 sb = smem_u32(smem);
    float* sP = (float*)(smem + SP_OFF2);
    volatile unsigned* pcnt = (volatile unsigned*)(smem + PCNT_OFF);

    const int dir   = blockIdx.x >> 6;
    const int rg    = (blockIdx.x >> 5) & 1;
    const int hg    = blockIdx.x & 31;
    const int hTile = hg * 16;
    const __nv_bfloat16* __restrict__ wth = g_wth[dir];
    const __nv_bfloat16* __restrict__ wtl = g_wtl[dir];

    const int tid = threadIdx.x;
    const int wid = tid >> 5, lane = tid & 31;
    const int l7 = lane & 7, sub = lane >> 3;
    const int gr = lane >> 2, tg = lane & 3;

    if (tid == 0) *pcnt = 0u;

    // Stage B_r (resident): n = q16*16 + g2*8 + hc8 -> gate=(q16&1)*2+g2, hcl=(q16>>1)*8+hc8
    for (int i = tid; i < 64 * 64; i += 384) {
        int n = i >> 6, kq = i & 63;
        int q16 = n >> 4, g2 = (n >> 3) & 1, hc8 = n & 7;
        int gate = (q16 & 1) * 2 + g2;
        int hcl = (q16 >> 1) * 8 + hc8;
        size_t ng = (size_t)(gate * H + hTile + hcl) * 1024 + 512 + kq * 8;
        uint4 vh = *(const uint4*)(wth + ng);
        uint4 vl = *(const uint4*)(wtl + ng);
        u32 dst = (u32)(n * 2048 + ((kq ^ (n & 7)) << 4));
        *(uint4*)(smem + B_OFF2 + dst)        = vh;
        *(uint4*)(smem + B_OFF2 + dst + 1024) = vl;
    }
    __syncthreads();

    if (wid < 8) {
        // =================== CONSUMER (recurrent LSTM) ===================
        const int mw = wid & 1, q = wid >> 1;
        const float* __restrict__ Z = dir ? g_ZB : g_ZF;
        const u32 aRowBase = sb + A_OFF2 + (u32)(mw * 16 + ((sub & 1) ? 8 : 0) + l7) * 2048;
        const int acbit = sub >> 1;
        const u32 bRowBase = sb + B_OFF2 + (u32)(q * 16 + ((sub & 2) ? 8 : 0) + l7) * 2048;
        const int bcbit = sub & 1;
        const int X = l7;

        unsigned* flags = &g_flag[dir][rg][0];
        unsigned* myflag = &g_flag[dir][rg][hg * 2];
        const int R0 = mw * 16 + gr;
        const int hcl0 = (q >> 1) * 8 + tg * 2;
        const int nh = q & 1;
        const int g0 = nh * 2;
        const int hidx = (wid >> 1) * 32 + lane;
        const int halfbar = 1 + mw;
        const int pairbar = 3 + mw * 2 + (q >> 1);

        // bias (Z no longer contains it)
        const float* bias = dir ? bbw : bfw;
        const float bA0 = bias[g0 * H + hTile + hcl0];
        const float bA1 = bias[g0 * H + hTile + hcl0 + 1];
        const float bB0 = bias[(g0 + 1) * H + hTile + hcl0];
        const float bB1 = bias[(g0 + 1) * H + hTile + hcl0 + 1];

        float c0x = 0.f, c0y = 0.f, c1x = 0.f, c1y = 0.f;

        for (int s = 0; s < T; s++) {
            if (s > 0) {
                unsigned tgt = 4u * (unsigned)s;
                for (;;) {
                    unsigned v = ld_acquire(flags + (lane << 1));
                    if (__all_sync(0xffffffffu, v >= tgt)) break;
                }
            }
            // Z availability from producer warps (usually already true)
            while (*pcnt <= (unsigned)s) { }
            asm volatile("membar.cta;" ::: "memory");

            const int t = dir ? (T - 1 - s) : s;
            const int grow = rg * 32 + R0;

            const float* zp = Z + ((size_t)t * Bsz + grow) * NG + g0 * H + hTile + hcl0;
            float2 zA0 = __ldcg((const float2*)zp);
            float2 zB0 = __ldcg((const float2*)(zp + H));
            float2 zA1 = __ldcg((const float2*)(zp + 8 * NG));
            float2 zB1 = __ldcg((const float2*)(zp + 8 * NG + H));
            zA0.x += bA0; zA0.y += bA1; zA1.x += bA0; zA1.y += bA1;
            zB0.x += bB0; zB0.y += bB1; zB1.x += bB0; zB1.y += bB1;

            // Stage A_r: each mw-half stages its own 16 rows
            {
                const __nv_bfloat16* hh = g_hh[s & 1][dir] + (rg * 32 + mw * 16) * H;
                const __nv_bfloat16* hl = g_hl[s & 1][dir] + (rg * 32 + mw * 16) * H;
#pragma unroll
                for (int j = 0; j < 8; j++) {
                    int g = hidx + j * 128;
                    int r = g >> 6, kq = g & 63;
                    int rfull = mw * 16 + r;
                    u32 dst = sb + A_OFF2 + (u32)(rfull * 2048 + ((kq ^ (rfull & 7)) << 4));
                    CP16(dst,        hh + r * 512 + kq * 8);
                    CP16(dst + 1024, hl + r * 512 + kq * 8);
                }
            }
            CP_COMMIT;
            CP_WAIT0;
            BAR_SYNC(halfbar, 128);

            float d0[4] = {0.f, 0.f, 0.f, 0.f}, d1[4] = {0.f, 0.f, 0.f, 0.f};
#pragma unroll 8
            for (int kt = 0; kt < 32; kt++) {
                int ca = (kt << 1) | acbit;
                int cb = (kt << 1) | bcbit;
                u32 ah[4], al[4], bh[4], bl[4];
                ldm4(ah, aRowBase + (u32)((ca ^ X) << 4));
                ldm4(al, aRowBase + (u32)(((ca + 64) ^ X) << 4));
                ldm4(bh, bRowBase + (u32)((cb ^ X) << 4));
                ldm4(bl, bRowBase + (u32)(((cb + 64) ^ X) << 4));
                mma_bf16(d0, ah, bh[0], bh[1]);
                mma_bf16(d1, ah, bh[2], bh[3]);
                mma_bf16(d0, al, bh[0], bh[1]);
                mma_bf16(d1, al, bh[2], bh[3]);
                mma_bf16(d0, ah, bl[0], bl[1]);
                mma_bf16(d1, ah, bl[2], bl[3]);
            }

            if (nh == 0) {
                float2 p0, p1;
                p0.x = sigf(d0[0] + zA0.x) * tanh_fast(d1[0] + zB0.x);
                p0.y = sigf(d0[1] + zA0.y) * tanh_fast(d1[1] + zB0.y);
                p1.x = sigf(d0[2] + zA1.x) * tanh_fast(d1[2] + zB1.x);
                p1.y = sigf(d0[3] + zA1.y) * tanh_fast(d1[3] + zB1.y);
                *(float2*)&sP[R0 * 16 + hcl0]       = p0;
                *(float2*)&sP[(R0 + 8) * 16 + hcl0] = p1;
                BAR_SYNC(pairbar, 64);
            } else {
                float Fv[4], Ov[4];
                Fv[0] = sigf(d0[0] + zA0.x + 1.f); Fv[1] = sigf(d0[1] + zA0.y + 1.f);
                Fv[2] = sigf(d0[2] + zA1.x + 1.f); Fv[3] = sigf(d0[3] + zA1.y + 1.f);
                Ov[0] = sigf(d1[0] + zB0.x); Ov[1] = sigf(d1[1] + zB0.y);
                Ov[2] = sigf(d1[2] + zB1.x); Ov[3] = sigf(d1[3] + zB1.y);
                BAR_SYNC(pairbar, 64);

                float2 P0 = *(const float2*)&sP[R0 * 16 + hcl0];
                float2 P1 = *(const float2*)&sP[(R0 + 8) * 16 + hcl0];
                c0x = Fv[0] * c0x + P0.x; c0y = Fv[1] * c0y + P0.y;
                c1x = Fv[2] * c1x + P1.x; c1y = Fv[3] * c1y + P1.y;
                float h0x = Ov[0] * tanh_fast(c0x), h0y = Ov[1] * tanh_fast(c0y);
                float h1x = Ov[2] * tanh_fast(c1x), h1y = Ov[3] * tanh_fast(c1y);

                u16 ha0, la0, ha1, la1, hb0, lb0, hb1, lb1;
                split_bf16(h0x, ha0, la0); split_bf16(h0y, ha1, la1);
                split_bf16(h1x, hb0, lb0); split_bf16(h1y, hb1, lb1);
                int pp = (s & 1) ^ 1;
                u32 o0 = (u32)(grow * H + hTile + hcl0);
                u32 o1 = o0 + 8 * H;
                *(u32*)&g_hh[pp][dir][o0] = (u32)ha0 | ((u32)ha1 << 16);
                *(u32*)&g_hl[pp][dir][o0] = (u32)la0 | ((u32)la1 << 16);
                *(u32*)&g_hh[pp][dir][o1] = (u32)hb0 | ((u32)hb1 << 16);
                *(u32*)&g_hl[pp][dir][o1] = (u32)lb0 | ((u32)lb1 << 16);

                __syncwarp();
                if (lane == 0) red_release_add(myflag, 1u);

                *(float2*)(out + ((size_t)grow * T + t) * (2 * H) + dir * H + hTile + hcl0)
                    = make_float2(h0x, h0y);
                *(float2*)(out + ((size_t)(grow + 8) * T + t) * (2 * H) + dir * H + hTile + hcl0)
                    = make_float2(h1x, h1y);
            }
        }
    } else {
        // =================== PRODUCER (Z = x @ Wx slice) ===================
        const int ptid = tid - 256;        // 0..127
        const int pwarp = wid - 8;         // 0..3
        const int pw = pwarp & 1;          // row half (16 rows)
        const int ph = pwarp >> 1;         // col half (32 n-cols)
        float* __restrict__ Zo = dir ? g_ZB : g_ZF;

        const int pa_r = pw * 16 + ((sub & 1) ? 8 : 0) + l7;
        const u32 paBase = sb + PA_OFF + (u32)pa_r * 128;

        const int sAr = ptid >> 3;         // staging: A row pairs
        const int sAc = ptid & 7;

        for (int i = 0; i < T; i++) {
            const int t = dir ? (T - 1 - i) : i;
            const __nv_bfloat16* xh = g_xh + ((size_t)t * Bsz + rg * 32) * D;
            const __nv_bfloat16* xl = g_xl + ((size_t)t * Bsz + rg * 32) * D;

            float d[4][4];
#pragma unroll
            for (int f = 0; f < 4; f++)
#pragma unroll
                for (int e = 0; e < 4; e++) d[f][e] = 0.f;

            for (int kc = 0; kc < 8; kc++) {
                BAR_SYNC(7, 128);   // prior chunk's reads complete
                // stage A chunk: 32 rows x 64 k (hi+lo)
#pragma unroll
                for (int it = 0; it < 2; it++) {
                    int idx = ptid + it * 128;      // 0..255
                    int r = idx >> 3, cq = idx & 7;
                    u32 dst = sb + PA_OFF + (u32)(r * 128 + ((cq ^ (r & 7)) << 4));
                    CP16(dst,        xh + r * D + kc * 64 + cq * 8);
                    CP16(dst + 4096, xl + r * D + kc * 64 + cq * 8);
                }
                // stage B chunk: 64 n x 64 k (hi+lo); n = gate*16 + hcl
#pragma unroll
                for (int it = 0; it < 4; it++) {
                    int idx = ptid + it * 128;      // 0..511
                    int n = idx >> 3, cq = idx & 7;
                    int gate = n >> 4, hcl = n & 15;
                    size_t src = (size_t)(gate * H + hTile + hcl) * 1024 + kc * 64 + cq * 8;
                    u32 dst = sb + PB_OFF + (u32)(n * 128 + ((cq ^ (n & 7)) << 4));
                    CP16(dst,        wth + src);
                    CP16(dst + 8192, wtl + src);
                }
                CP_COMMIT;
                CP_WAIT0;
                BAR_SYNC(7, 128);

#pragma unroll
                for (int kt = 0; kt < 4; kt++) {
                    int ca = kt * 2 + (sub >> 1);
                    u32 aoff = (u32)((ca ^ l7) << 4);
                    u32 ah[4], al[4];
                    ldm4(ah, paBase + aoff);
                    ldm4(al, paBase + 4096 + aoff);
#pragma unroll
                    for (int j = 0; j < 2; j++) {
                        int nb = ph * 32 + j * 16 + ((sub & 2) ? 8 : 0) + l7;
                        int cb = kt * 2 + (sub & 1);
                        u32 boff = (u32)(nb * 128 + ((cb ^ (nb & 7)) << 4));
                        u32 bh[4], bl[4];
                        ldm4(bh, sb + PB_OFF + boff);
                        ldm4(bl, sb + PB_OFF + 8192 + boff);
                        mma_bf16(d[j*2],   ah, bh[0], bh[1]);
                        mma_bf16(d[j*2+1], ah, bh[2], bh[3]);
                        mma_bf16(d[j*2],   al, bh[0], bh[1]);
                        mma_bf16(d[j*2+1], al, bh[2], bh[3]);
                        mma_bf16(d[j*2],   ah, bl[0], bl[1]);
                        mma_bf16(d[j*2+1], ah, bl[2], bl[3]);
                    }
                }
            }

            // store Z slice (no bias; consumer adds it)
            const int prow0 = rg * 32 + pw * 16 + gr;
#pragma unroll
            for (int f = 0; f < 4; f++) {
                int ln = ph * 32 + f * 8 + tg * 2;
                int gate = ln >> 4, hcl = ln & 15;
                size_t base = ((size_t)t * Bsz + prow0) * NG + gate * H + hTile + hcl;
                __stcg((float2*)(Zo + base),          make_float2(d[f][0], d[f][1]));
                __stcg((float2*)(Zo + base + 8 * NG), make_float2(d[f][2], d[f][3]));
            }
            __threadfence();
            BAR_SYNC(7, 128);
            if (ptid == 0) *pcnt = (unsigned)(i + 1);
        }
    }
}

extern "C" void kernel_launch(void* const* d_in, const int* in_sizes, int n_in,
                              void* d_out, int out_size) {
    const float* x    = (const float*)d_in[0];
    const float* W_fw = (const float*)d_in[1];
    const float* b_fw = (const float*)d_in[2];
    const float* W_bw = (const float*)d_in[3];
    const float* b_bw = (const float*)d_in[4];
    float* out = (float*)d_out;

    (void)in_sizes; (void)n_in; (void)out_size;

    cudaFuncSetAttribute(lstm_persistent,
                         cudaFuncAttributeMaxDynamicSharedMemorySize, P2_SMEM);

    init_kernel<<<(Bsz * H + 255) / 256, 256>>>();
    split_x_kernel<<<MTOT * 64 / 256, 256>>>(x);
    split_w_kernel<<<dim3(32, 64, 2), 256>>>(W_fw, W_bw);

    lstm_persistent<<<128, 384, P2_SMEM>>>(out, b_fw, b_bw);
}

// round 11
// speedup vs baseline: 1.3307x; 1.3307x over previous
#include <cuda_runtime.h>
#include <cuda_bf16.h>
#include <math.h>

#define Bsz 64
#define T 512
#define D 512
#define H 512
#define NG 2048  // 4*H
#define MTOT (Bsz*T)  // 32768

typedef unsigned long long u64;
typedef unsigned int u32;
typedef unsigned short u16;

// ---- common helpers ----
__device__ __forceinline__ u32 smem_u32(const void* p) {
    u32 a;
    asm("{ .reg .u64 t; cvta.to.shared.u64 t, %1; cvt.u32.u64 %0, t; }" : "=r"(a) : "l"(p));
    return a;
}
__device__ __forceinline__ void ldm4(u32* r, u32 p) {
    asm volatile("ldmatrix.sync.aligned.m8n8.x4.shared.b16 {%0,%1,%2,%3}, [%4];"
        : "=r"(r[0]), "=r"(r[1]), "=r"(r[2]), "=r"(r[3]) : "r"(p));
}
__device__ __forceinline__ void mma_bf16(float* d, const u32* a, u32 b0, u32 b1) {
    asm volatile("mma.sync.aligned.m16n8k16.row.col.f32.bf16.bf16.f32 "
        "{%0,%1,%2,%3}, {%4,%5,%6,%7}, {%8,%9}, {%0,%1,%2,%3};"
        : "+f"(d[0]), "+f"(d[1]), "+f"(d[2]), "+f"(d[3])
        : "r"(a[0]), "r"(a[1]), "r"(a[2]), "r"(a[3]), "r"(b0), "r"(b1));
}
__device__ __forceinline__ void split_bf16(float x, u16& hb, u16& lb) {
    __nv_bfloat16 h = __float2bfloat16_rn(x);
    hb = __bfloat16_as_ushort(h);
    lb = __bfloat16_as_ushort(__float2bfloat16_rn(x - __bfloat162float(h)));
}
__device__ __forceinline__ float sigf(float x) {
    float e, r;
    asm("ex2.approx.f32 %0, %1;" : "=f"(e) : "f"(-x * 1.4426950408889634f));
    asm("rcp.approx.f32 %0, %1;" : "=f"(r) : "f"(1.0f + e));
    return r;
}
__device__ __forceinline__ float tanh_fast(float x) {
    return fmaf(2.f, sigf(2.f * x), -1.f);
}
__device__ __forceinline__ void red_release_add(unsigned* p, unsigned v) {
    asm volatile("red.release.gpu.global.add.u32 [%0], %1;" :: "l"(p), "r"(v) : "memory");
}
__device__ __forceinline__ unsigned ld_acquire(const unsigned* p) {
    unsigned v;
    asm volatile("ld.acquire.gpu.global.u32 %0, [%1];" : "=r"(v) : "l"(p) : "memory");
    return v;
}
#define CP16(dst, src) \
    asm volatile("cp.async.cg.shared.global [%0], [%1], 16;" :: "r"(dst), "l"(src))
#define CP_COMMIT asm volatile("cp.async.commit_group;")
#define BAR_SYNC(id, cnt) asm volatile("bar.sync %0, %1;" :: "r"(id), "r"(cnt) : "memory")

// ---- scratch ----
__device__ float g_ZF[(size_t)T * Bsz * NG];
__device__ float g_ZB[(size_t)T * Bsz * NG];
__device__ __align__(16) __nv_bfloat16 g_hh[2][2][Bsz * H];
__device__ __align__(16) __nv_bfloat16 g_hl[2][2][Bsz * H];
__device__ __align__(16) __nv_bfloat16 g_xh[(size_t)MTOT * D];   // row m = t*B + b
__device__ __align__(16) __nv_bfloat16 g_xl[(size_t)MTOT * D];
__device__ __align__(16) __nv_bfloat16 g_wth[2][(size_t)NG * 1024]; // [dir][n][k]
__device__ __align__(16) __nv_bfloat16 g_wtl[2][(size_t)NG * 1024];
__device__ unsigned g_bar2[2][2];      // [dir][rg]

__global__ void init_kernel() {
    int i = blockIdx.x * blockDim.x + threadIdx.x;
    if (i < Bsz * H) {
        __nv_bfloat16 z = __float2bfloat16(0.f);
        g_hh[0][0][i] = z; g_hh[0][1][i] = z; g_hh[1][0][i] = z; g_hh[1][1][i] = z;
        g_hl[0][0][i] = z; g_hl[0][1][i] = z; g_hl[1][0][i] = z; g_hl[1][1][i] = z;
    }
    if (i < 2) { g_bar2[i][0] = 0u; g_bar2[i][1] = 0u; }
}

__global__ void __launch_bounds__(256) split_x_kernel(const float* __restrict__ x) {
    int id = blockIdx.x * 256 + threadIdx.x;
    int m = id >> 6, c8 = id & 63;
    int b = m & (Bsz - 1), t = m >> 6;
    const float4* xp = (const float4*)(x + ((size_t)b * T + t) * D + c8 * 8);
    float4 v0 = xp[0], v1 = xp[1];
    u16 h[8], l[8];
    split_bf16(v0.x, h[0], l[0]); split_bf16(v0.y, h[1], l[1]);
    split_bf16(v0.z, h[2], l[2]); split_bf16(v0.w, h[3], l[3]);
    split_bf16(v1.x, h[4], l[4]); split_bf16(v1.y, h[5], l[5]);
    split_bf16(v1.z, h[6], l[6]); split_bf16(v1.w, h[7], l[7]);
    uint4 ph, pl;
    ph.x = (u32)h[0] | ((u32)h[1] << 16); ph.y = (u32)h[2] | ((u32)h[3] << 16);
    ph.z = (u32)h[4] | ((u32)h[5] << 16); ph.w = (u32)h[6] | ((u32)h[7] << 16);
    pl.x = (u32)l[0] | ((u32)l[1] << 16); pl.y = (u32)l[2] | ((u32)l[3] << 16);
    pl.z = (u32)l[4] | ((u32)l[5] << 16); pl.w = (u32)l[6] | ((u32)l[7] << 16);
    *(uint4*)(g_xh + (size_t)m * D + c8 * 8) = ph;
    *(uint4*)(g_xl + (size_t)m * D + c8 * 8) = pl;
}

__global__ void __launch_bounds__(256) split_w_kernel(
    const float* __restrict__ Wfw, const float* __restrict__ Wbw) {
    __shared__ float tile[32][33];
    int dir = blockIdx.z;
    int k0 = blockIdx.x * 32, n0 = blockIdx.y * 32;
    const float* W = dir ? Wbw : Wfw;
    int tid = threadIdx.x;
#pragma unroll
    for (int i = 0; i < 4; i++) {
        int idx = tid + i * 256;
        int r = idx >> 5, c = idx & 31;
        tile[r][c] = W[(size_t)(k0 + r) * NG + n0 + c];
    }
    __syncthreads();
#pragma unroll
    for (int i = 0; i < 4; i++) {
        int idx = tid + i * 256;
        int r = idx >> 5, c = idx & 31;
        u16 hb, lb; split_bf16(tile[c][r], hb, lb);
        size_t o = (size_t)(n0 + r) * 1024 + k0 + c;
        g_wth[dir][o] = __ushort_as_bfloat16(hb);
        g_wtl[dir][o] = __ushort_as_bfloat16(lb);
    }
}

// ---------------------------------------------------------------------------
// Phase 1: Z = x @ W[:D] + b, bf16-split mma.sync — unchanged (956us, tensor 71%).
// ---------------------------------------------------------------------------
#define G1_BUF 65536
#define G1_SMEM (2 * G1_BUF)

__global__ void __launch_bounds__(256, 1) gemm_x_mma(
    const float* __restrict__ bfw, const float* __restrict__ bbw)
{
    extern __shared__ char smem[];
    const u32 sb = smem_u32(smem);
    const int tid = threadIdx.x;
    const int wid = tid >> 5, lane = tid & 31;
    const int mw = wid & 3, nw = wid >> 2;
    const int l7 = lane & 7, sub = lane >> 3, gr = lane >> 2, tg = lane & 3;

    const int bm = blockIdx.y * 128;
    const int bn = blockIdx.x * 128;
    const int dir = bn >= 2048;
    const int n0 = bn - dir * 2048;
    const __nv_bfloat16* __restrict__ wth = g_wth[dir];
    const __nv_bfloat16* __restrict__ wtl = g_wtl[dir];

    const int sr = tid >> 3;
    const int sc = tid & 7;

    const u32 rowA0 = (u32)(mw * 32 + (sub & 1) * 8 + l7);
    const u32 rowA1 = rowA0 + 16;
    const int acbit = sub >> 1;
    const u32 rB0 = (u32)(nw * 64 + ((sub & 2) ? 8 : 0) + l7);
    const int bcbit = sub & 1;

    float acc[2][8][4];
#pragma unroll
    for (int i = 0; i < 2; i++)
#pragma unroll
        for (int j = 0; j < 8; j++)
#pragma unroll
            for (int q = 0; q < 4; q++) acc[i][j][q] = 0.f;

    auto stage = [&](int kk, u32 base) {
#pragma unroll
        for (int j = 0; j < 4; j++) {
            int r = sr + j * 32;
            u32 dst = base + (u32)(r * 128 + ((sc ^ (r & 7)) << 4));
            size_t ao = (size_t)(bm + r) * D + kk * 64 + sc * 8;
            CP16(dst,          g_xh + ao);
            CP16(dst + 16384,  g_xl + ao);
            size_t bo = (size_t)(n0 + r) * 1024 + kk * 64 + sc * 8;
            CP16(dst + 32768,  wth + bo);
            CP16(dst + 49152,  wtl + bo);
        }
    };

    stage(0, sb);
    CP_COMMIT;

    for (int kk = 0; kk < 8; kk++) {
        u32 buf = sb + (u32)(kk & 1) * G1_BUF;
        if (kk < 7) {
            stage(kk + 1, sb + (u32)((kk + 1) & 1) * G1_BUF);
            CP_COMMIT;
            asm volatile("cp.async.wait_group 1;");
        } else {
            asm volatile("cp.async.wait_group 0;");
        }
        __syncthreads();
#pragma unroll
        for (int q = 0; q < 4; q++) {
            int ca = 2 * q + acbit;
            u32 a0[4], a1[4], al0[4], al1[4];
            u32 aoff0 = rowA0 * 128 + (u32)((ca ^ (rowA0 & 7)) << 4);
            u32 aoff1 = rowA1 * 128 + (u32)((ca ^ (rowA1 & 7)) << 4);
            ldm4(a0,  buf + aoff0);
            ldm4(a1,  buf + aoff1);
            ldm4(al0, buf + 16384 + aoff0);
            ldm4(al1, buf + 16384 + aoff1);
            int cb = 2 * q + bcbit;
#pragma unroll
            for (int j = 0; j < 4; j++) {
                u32 rB = rB0 + (u32)(j * 16);
                u32 boff = rB * 128 + (u32)((cb ^ (rB & 7)) << 4);
                u32 bh[4], bl[4];
                ldm4(bh, buf + 32768 + boff);
                ldm4(bl, buf + 49152 + boff);
                mma_bf16(acc[0][2*j],   a0,  bh[0], bh[1]);
                mma_bf16(acc[0][2*j+1], a0,  bh[2], bh[3]);
                mma_bf16(acc[1][2*j],   a1,  bh[0], bh[1]);
                mma_bf16(acc[1][2*j+1], a1,  bh[2], bh[3]);
                mma_bf16(acc[0][2*j],   al0, bh[0], bh[1]);
                mma_bf16(acc[0][2*j+1], al0, bh[2], bh[3]);
                mma_bf16(acc[1][2*j],   al1, bh[0], bh[1]);
                mma_bf16(acc[1][2*j+1], al1, bh[2], bh[3]);
                mma_bf16(acc[0][2*j],   a0,  bl[0], bl[1]);
                mma_bf16(acc[0][2*j+1], a0,  bl[2], bl[3]);
                mma_bf16(acc[1][2*j],   a1,  bl[0], bl[1]);
                mma_bf16(acc[1][2*j+1], a1,  bl[2], bl[3]);
            }
        }
        __syncthreads();
    }

    float* __restrict__ Zo = dir ? g_ZB : g_ZF;
    const float* __restrict__ bias = dir ? bbw : bfw;
#pragma unroll
    for (int am = 0; am < 2; am++) {
        int m0 = bm + mw * 32 + am * 16 + gr;
#pragma unroll
        for (int p = 0; p < 8; p++) {
            int nc = n0 + nw * 64 + p * 8 + tg * 2;
            float bx = bias[nc], by = bias[nc + 1];
            const float* a = acc[am][p];
            *(float2*)(Zo + (size_t)m0 * NG + nc)       = make_float2(a[0] + bx, a[1] + by);
            *(float2*)(Zo + (size_t)(m0 + 8) * NG + nc) = make_float2(a[2] + bx, a[3] + by);
        }
    }
}

// ---------------------------------------------------------------------------
// Phase 2 v5 (R8 base + latency cuts):
// - Z prefetch hoisted above the flag spin (hides L2/DRAM latency)
// - A staging split into 2 k-halves (cp.async groups); mma pipelined vs half 2
// - cell state in registers; central per-(dir,rg) release counter (R8, best)
// ---------------------------------------------------------------------------
#define A_OFF2 0
#define B_OFF2 65536
#define SP_OFF2 (B_OFF2 + 131072)      // 2KB P handoff
#define P2_SMEM (SP_OFF2 + 2048 + 64)

__global__ void __launch_bounds__(256, 1) lstm_persistent(float* __restrict__ out)
{
    extern __shared__ char smem[];
    const u32 sb = smem_u32(smem);
    float* sP = (float*)(smem + SP_OFF2);

    const int dir   = blockIdx.x >> 6;
    const int rg    = (blockIdx.x >> 5) & 1;
    const int hTile = (blockIdx.x & 31) * 16;
    const float* __restrict__ Z = dir ? g_ZB : g_ZF;
    const __nv_bfloat16* __restrict__ wth = g_wth[dir];
    const __nv_bfloat16* __restrict__ wtl = g_wtl[dir];

    const int tid = threadIdx.x;
    const int wid = tid >> 5, lane = tid & 31;
    const int mw = wid & 1, q = wid >> 1;
    const int l7 = lane & 7, sub = lane >> 3;
    const int gr = lane >> 2, tg = lane & 3;

    const u32 aRowBase = sb + A_OFF2 + (u32)(mw * 16 + ((sub & 1) ? 8 : 0) + l7) * 2048;
    const int acbit = sub >> 1;
    const u32 bRowBase = sb + B_OFF2 + (u32)(q * 16 + ((sub & 2) ? 8 : 0) + l7) * 2048;
    const int bcbit = sub & 1;
    const int X = l7;

    // Stage B (resident)
    for (int i = tid; i < 64 * 64; i += 256) {
        int n = i >> 6, kq = i & 63;
        int q16 = n >> 4, g2 = (n >> 3) & 1, hc8 = n & 7;
        int gate = (q16 & 1) * 2 + g2;
        int hcl = (q16 >> 1) * 8 + hc8;
        size_t ng = (size_t)(gate * H + hTile + hcl) * 1024 + 512 + kq * 8;
        uint4 vh = *(const uint4*)(wth + ng);
        uint4 vl = *(const uint4*)(wtl + ng);
        u32 dst = (u32)(n * 2048 + ((kq ^ (n & 7)) << 4));
        *(uint4*)(smem + B_OFF2 + dst)        = vh;
        *(uint4*)(smem + B_OFF2 + dst + 1024) = vl;
    }
    __syncthreads();

    unsigned* bar = &g_bar2[dir][rg];
    const int R0 = mw * 16 + gr;
    const int hcl0 = (q >> 1) * 8 + tg * 2;
    const int nh = q & 1;
    const int g0 = nh * 2;
    const int hidx = (wid >> 1) * 32 + lane;  // 0..127 within mw-half
    const int halfbar = 1 + mw;
    const int pairbar = 3 + mw * 2 + (q >> 1);

    float c0x = 0.f, c0y = 0.f, c1x = 0.f, c1y = 0.f;

    for (int s = 0; s < T; s++) {
        const int t = dir ? (T - 1 - s) : s;
        const int grow = rg * 32 + R0;

        // Z prefetch BEFORE spin: independent of flags, hides L2/DRAM latency
        const float* zp = Z + ((size_t)t * Bsz + grow) * NG + g0 * H + hTile + hcl0;
        float2 zA0 = __ldcg((const float2*)zp);
        float2 zB0 = __ldcg((const float2*)(zp + H));
        float2 zA1 = __ldcg((const float2*)(zp + 8 * NG));
        float2 zB1 = __ldcg((const float2*)(zp + 8 * NG + H));

        if (s > 0) {
            unsigned target = 128u * (unsigned)s;
            while (ld_acquire(bar) < target) { }
        }

        // Stage A in two k-halves; pipeline second half against first mma half
        const __nv_bfloat16* hh = g_hh[s & 1][dir] + (rg * 32 + mw * 16) * H;
        const __nv_bfloat16* hl = g_hl[s & 1][dir] + (rg * 32 + mw * 16) * H;
#pragma unroll
        for (int j = 0; j < 4; j++) {                 // k-half 0: kq 0..31
            int local = hidx + j * 128;               // 0..511
            int r = local >> 5, kq = local & 31;
            int rfull = mw * 16 + r;
            u32 dst = sb + A_OFF2 + (u32)(rfull * 2048 + ((kq ^ (rfull & 7)) << 4));
            CP16(dst,        hh + r * 512 + kq * 8);
            CP16(dst + 1024, hl + r * 512 + kq * 8);
        }
        CP_COMMIT;
#pragma unroll
        for (int j = 0; j < 4; j++) {                 // k-half 1: kq 32..63
            int local = hidx + j * 128;
            int r = local >> 5, kq = 32 + (local & 31);
            int rfull = mw * 16 + r;
            u32 dst = sb + A_OFF2 + (u32)(rfull * 2048 + ((kq ^ (rfull & 7)) << 4));
            CP16(dst,        hh + r * 512 + kq * 8);
            CP16(dst + 1024, hl + r * 512 + kq * 8);
        }
        CP_COMMIT;
        asm volatile("cp.async.wait_group 1;");
        BAR_SYNC(halfbar, 128);

        float d0[4] = {0.f, 0.f, 0.f, 0.f}, d1[4] = {0.f, 0.f, 0.f, 0.f};
#pragma unroll 8
        for (int kt = 0; kt < 16; kt++) {             // uses kq 0..31 (hi+lo)
            int ca = (kt << 1) | acbit;
            int cb = (kt << 1) | bcbit;
            u32 ah[4], al[4], bh[4], bl[4];
            ldm4(ah, aRowBase + (u32)((ca ^ X) << 4));
            ldm4(al, aRowBase + (u32)(((ca + 64) ^ X) << 4));
            ldm4(bh, bRowBase + (u32)((cb ^ X) << 4));
            ldm4(bl, bRowBase + (u32)(((cb + 64) ^ X) << 4));
            mma_bf16(d0, ah, bh[0], bh[1]);
            mma_bf16(d1, ah, bh[2], bh[3]);
            mma_bf16(d0, al, bh[0], bh[1]);
            mma_bf16(d1, al, bh[2], bh[3]);
            mma_bf16(d0, ah, bl[0], bl[1]);
            mma_bf16(d1, ah, bl[2], bl[3]);
        }
        asm volatile("cp.async.wait_group 0;");
        BAR_SYNC(halfbar, 128);
#pragma unroll 8
        for (int kt = 16; kt < 32; kt++) {            // uses kq 32..63 (hi+lo)
            int ca = (kt << 1) | acbit;
            int cb = (kt << 1) | bcbit;
            u32 ah[4], al[4], bh[4], bl[4];
            ldm4(ah, aRowBase + (u32)((ca ^ X) << 4));
            ldm4(al, aRowBase + (u32)(((ca + 64) ^ X) << 4));
            ldm4(bh, bRowBase + (u32)((cb ^ X) << 4));
            ldm4(bl, bRowBase + (u32)(((cb + 64) ^ X) << 4));
            mma_bf16(d0, ah, bh[0], bh[1]);
            mma_bf16(d1, ah, bh[2], bh[3]);
            mma_bf16(d0, al, bh[0], bh[1]);
            mma_bf16(d1, al, bh[2], bh[3]);
            mma_bf16(d0, ah, bl[0], bl[1]);
            mma_bf16(d1, ah, bl[2], bl[3]);
        }

        // Epilogue: nh0 -> P = sig(i)*tanh(j); pair barrier; nh1 -> c/h
        if (nh == 0) {
            float2 p0, p1;
            p0.x = sigf(d0[0] + zA0.x) * tanh_fast(d1[0] + zB0.x);
            p0.y = sigf(d0[1] + zA0.y) * tanh_fast(d1[1] + zB0.y);
            p1.x = sigf(d0[2] + zA1.x) * tanh_fast(d1[2] + zB1.x);
            p1.y = sigf(d0[3] + zA1.y) * tanh_fast(d1[3] + zB1.y);
            *(float2*)&sP[R0 * 16 + hcl0]       = p0;
            *(float2*)&sP[(R0 + 8) * 16 + hcl0] = p1;
            BAR_SYNC(pairbar, 64);
        } else {
            float Fv[4], Ov[4];
            Fv[0] = sigf(d0[0] + zA0.x + 1.f); Fv[1] = sigf(d0[1] + zA0.y + 1.f);
            Fv[2] = sigf(d0[2] + zA1.x + 1.f); Fv[3] = sigf(d0[3] + zA1.y + 1.f);
            Ov[0] = sigf(d1[0] + zB0.x); Ov[1] = sigf(d1[1] + zB0.y);
            Ov[2] = sigf(d1[2] + zB1.x); Ov[3] = sigf(d1[3] + zB1.y);
            BAR_SYNC(pairbar, 64);

            float2 P0 = *(const float2*)&sP[R0 * 16 + hcl0];
            float2 P1 = *(const float2*)&sP[(R0 + 8) * 16 + hcl0];
            c0x = Fv[0] * c0x + P0.x; c0y = Fv[1] * c0y + P0.y;
            c1x = Fv[2] * c1x + P1.x; c1y = Fv[3] * c1y + P1.y;
            float h0x = Ov[0] * tanh_fast(c0x), h0y = Ov[1] * tanh_fast(c0y);
            float h1x = Ov[2] * tanh_fast(c1x), h1y = Ov[3] * tanh_fast(c1y);

            u16 ha0, la0, ha1, la1, hb0, lb0, hb1, lb1;
            split_bf16(h0x, ha0, la0); split_bf16(h0y, ha1, la1);
            split_bf16(h1x, hb0, lb0); split_bf16(h1y, hb1, lb1);
            int pp = (s & 1) ^ 1;
            u32 o0 = (u32)(grow * H + hTile + hcl0);
            u32 o1 = o0 + 8 * H;
            *(u32*)&g_hh[pp][dir][o0] = (u32)ha0 | ((u32)ha1 << 16);
            *(u32*)&g_hl[pp][dir][o0] = (u32)la0 | ((u32)la1 << 16);
            *(u32*)&g_hh[pp][dir][o1] = (u32)hb0 | ((u32)hb1 << 16);
            *(u32*)&g_hl[pp][dir][o1] = (u32)lb0 | ((u32)lb1 << 16);

            __syncwarp();
            if (lane == 0) red_release_add(bar, 1u);

            // out stores off the critical path (after release)
            *(float2*)(out + ((size_t)grow * T + t) * (2 * H) + dir * H + hTile + hcl0)
                = make_float2(h0x, h0y);
            *(float2*)(out + ((size_t)(grow + 8) * T + t) * (2 * H) + dir * H + hTile + hcl0)
                = make_float2(h1x, h1y);
        }
    }
}

extern "C" void kernel_launch(void* const* d_in, const int* in_sizes, int n_in,
                              void* d_out, int out_size) {
    const float* x    = (const float*)d_in[0];
    const float* W_fw = (const float*)d_in[1];
    const float* b_fw = (const float*)d_in[2];
    const float* W_bw = (const float*)d_in[3];
    const float* b_bw = (const float*)d_in[4];
    float* out = (float*)d_out;

    (void)in_sizes; (void)n_in; (void)out_size;

    cudaFuncSetAttribute(gemm_x_mma,
                         cudaFuncAttributeMaxDynamicSharedMemorySize, G1_SMEM);
    cudaFuncSetAttribute(lstm_persistent,
                         cudaFuncAttributeMaxDynamicSharedMemorySize, P2_SMEM);

    init_kernel<<<(Bsz * H + 255) / 256, 256>>>();
    split_x_kernel<<<MTOT * 64 / 256, 256>>>(x);
    split_w_kernel<<<dim3(32, 64, 2), 256>>>(W_fw, W_bw);

    gemm_x_mma<<<dim3(32, 256), 256, G1_SMEM>>>(b_fw, b_bw);

    lstm_persistent<<<128, 256, P2_SMEM>>>(out);
}

// round 12
// speedup vs baseline: 1.3424x; 1.0088x over previous
#include <cuda_runtime.h>
#include <cuda_bf16.h>
#include <math.h>

#define Bsz 64
#define T 512
#define D 512
#define H 512
#define NG 2048  // 4*H
#define MTOT (Bsz*T)  // 32768

typedef unsigned long long u64;
typedef unsigned int u32;
typedef unsigned short u16;

// ---- common helpers ----
__device__ __forceinline__ u32 smem_u32(const void* p) {
    u32 a;
    asm("{ .reg .u64 t; cvta.to.shared.u64 t, %1; cvt.u32.u64 %0, t; }" : "=r"(a) : "l"(p));
    return a;
}
__device__ __forceinline__ void ldm4(u32* r, u32 p) {
    asm volatile("ldmatrix.sync.aligned.m8n8.x4.shared.b16 {%0,%1,%2,%3}, [%4];"
        : "=r"(r[0]), "=r"(r[1]), "=r"(r[2]), "=r"(r[3]) : "r"(p));
}
__device__ __forceinline__ void mma_bf16(float* d, const u32* a, u32 b0, u32 b1) {
    asm volatile("mma.sync.aligned.m16n8k16.row.col.f32.bf16.bf16.f32 "
        "{%0,%1,%2,%3}, {%4,%5,%6,%7}, {%8,%9}, {%0,%1,%2,%3};"
        : "+f"(d[0]), "+f"(d[1]), "+f"(d[2]), "+f"(d[3])
        : "r"(a[0]), "r"(a[1]), "r"(a[2]), "r"(a[3]), "r"(b0), "r"(b1));
}
__device__ __forceinline__ void split_bf16(float x, u16& hb, u16& lb) {
    __nv_bfloat16 h = __float2bfloat16_rn(x);
    hb = __bfloat16_as_ushort(h);
    lb = __bfloat16_as_ushort(__float2bfloat16_rn(x - __bfloat162float(h)));
}
__device__ __forceinline__ float sigf(float x) {
    float e, r;
    asm("ex2.approx.f32 %0, %1;" : "=f"(e) : "f"(-x * 1.4426950408889634f));
    asm("rcp.approx.f32 %0, %1;" : "=f"(r) : "f"(1.0f + e));
    return r;
}
__device__ __forceinline__ float tanh_fast(float x) {
    return fmaf(2.f, sigf(2.f * x), -1.f);
}
__device__ __forceinline__ void red_release_add(unsigned* p, unsigned v) {
    asm volatile("red.release.gpu.global.add.u32 [%0], %1;" :: "l"(p), "r"(v) : "memory");
}
__device__ __forceinline__ unsigned ld_acquire(const unsigned* p) {
    unsigned v;
    asm volatile("ld.acquire.gpu.global.u32 %0, [%1];" : "=r"(v) : "l"(p) : "memory");
    return v;
}
#define CP16(dst, src) \
    asm volatile("cp.async.cg.shared.global [%0], [%1], 16;" :: "r"(dst), "l"(src))
#define CP_COMMIT asm volatile("cp.async.commit_group;")
#define BAR_SYNC(id, cnt) asm volatile("bar.sync %0, %1;" :: "r"(id), "r"(cnt) : "memory")

// ---- scratch ----
__device__ float g_ZF[(size_t)T * Bsz * NG];
__device__ float g_ZB[(size_t)T * Bsz * NG];
__device__ __align__(16) __nv_bfloat16 g_hh[2][2][Bsz * H];
__device__ __align__(16) __nv_bfloat16 g_hl[2][2][Bsz * H];
__device__ __align__(16) __nv_bfloat16 g_xh[(size_t)MTOT * D];   // row m = t*B + b
__device__ __align__(16) __nv_bfloat16 g_xl[(size_t)MTOT * D];
__device__ __align__(16) __nv_bfloat16 g_wth[2][(size_t)NG * 1024]; // [dir][n][k]
__device__ __align__(16) __nv_bfloat16 g_wtl[2][(size_t)NG * 1024];
__device__ unsigned g_bar2[2][2];      // [dir][rg]

__global__ void init_kernel() {
    int i = blockIdx.x * blockDim.x + threadIdx.x;
    if (i < Bsz * H) {
        __nv_bfloat16 z = __float2bfloat16(0.f);
        g_hh[0][0][i] = z; g_hh[0][1][i] = z; g_hh[1][0][i] = z; g_hh[1][1][i] = z;
        g_hl[0][0][i] = z; g_hl[0][1][i] = z; g_hl[1][0][i] = z; g_hl[1][1][i] = z;
    }
    if (i < 2) { g_bar2[i][0] = 0u; g_bar2[i][1] = 0u; }
}

__global__ void __launch_bounds__(256) split_x_kernel(const float* __restrict__ x) {
    int id = blockIdx.x * 256 + threadIdx.x;
    int m = id >> 6, c8 = id & 63;
    int b = m & (Bsz - 1), t = m >> 6;
    const float4* xp = (const float4*)(x + ((size_t)b * T + t) * D + c8 * 8);
    float4 v0 = xp[0], v1 = xp[1];
    u16 h[8], l[8];
    split_bf16(v0.x, h[0], l[0]); split_bf16(v0.y, h[1], l[1]);
    split_bf16(v0.z, h[2], l[2]); split_bf16(v0.w, h[3], l[3]);
    split_bf16(v1.x, h[4], l[4]); split_bf16(v1.y, h[5], l[5]);
    split_bf16(v1.z, h[6], l[6]); split_bf16(v1.w, h[7], l[7]);
    uint4 ph, pl;
    ph.x = (u32)h[0] | ((u32)h[1] << 16); ph.y = (u32)h[2] | ((u32)h[3] << 16);
    ph.z = (u32)h[4] | ((u32)h[5] << 16); ph.w = (u32)h[6] | ((u32)h[7] << 16);
    pl.x = (u32)l[0] | ((u32)l[1] << 16); pl.y = (u32)l[2] | ((u32)l[3] << 16);
    pl.z = (u32)l[4] | ((u32)l[5] << 16); pl.w = (u32)l[6] | ((u32)l[7] << 16);
    *(uint4*)(g_xh + (size_t)m * D + c8 * 8) = ph;
    *(uint4*)(g_xl + (size_t)m * D + c8 * 8) = pl;
}

__global__ void __launch_bounds__(256) split_w_kernel(
    const float* __restrict__ Wfw, const float* __restrict__ Wbw) {
    __shared__ float tile[32][33];
    int dir = blockIdx.z;
    int k0 = blockIdx.x * 32, n0 = blockIdx.y * 32;
    const float* W = dir ? Wbw : Wfw;
    int tid = threadIdx.x;
#pragma unroll
    for (int i = 0; i < 4; i++) {
        int idx = tid + i * 256;
        int r = idx >> 5, c = idx & 31;
        tile[r][c] = W[(size_t)(k0 + r) * NG + n0 + c];
    }
    __syncthreads();
#pragma unroll
    for (int i = 0; i < 4; i++) {
        int idx = tid + i * 256;
        int r = idx >> 5, c = idx & 31;
        u16 hb, lb; split_bf16(tile[c][r], hb, lb);
        size_t o = (size_t)(n0 + r) * 1024 + k0 + c;
        g_wth[dir][o] = __ushort_as_bfloat16(hb);
        g_wtl[dir][o] = __ushort_as_bfloat16(lb);
    }
}

// ---------------------------------------------------------------------------
// Phase 1 v2: 3-stage cp.async pipeline, ONE __syncthreads per k-iter.
// Buffers: 3 x 64KB (Ah 0 | Al 16K | Bh 32K | Bl 48K each).
// Schedule per kk: wait_group(1) -> sync -> issue stage(kk+2) -> compute(kk).
// The sync publishes buf kk AND retires readers of buf (kk+2)%3 (= kk-1's buf).
// ---------------------------------------------------------------------------
#define G1_BUF 65536
#define G1_SMEM (3 * G1_BUF)

__global__ void __launch_bounds__(256, 1) gemm_x_mma(
    const float* __restrict__ bfw, const float* __restrict__ bbw)
{
    extern __shared__ char smem[];
    const u32 sb = smem_u32(smem);
    const int tid = threadIdx.x;
    const int wid = tid >> 5, lane = tid & 31;
    const int mw = wid & 3, nw = wid >> 2;
    const int l7 = lane & 7, sub = lane >> 3, gr = lane >> 2, tg = lane & 3;

    const int bm = blockIdx.y * 128;
    const int bn = blockIdx.x * 128;
    const int dir = bn >= 2048;
    const int n0 = bn - dir * 2048;
    const __nv_bfloat16* __restrict__ wth = g_wth[dir];
    const __nv_bfloat16* __restrict__ wtl = g_wtl[dir];

    const int sr = tid >> 3;
    const int sc = tid & 7;

    const u32 rowA0 = (u32)(mw * 32 + (sub & 1) * 8 + l7);
    const u32 rowA1 = rowA0 + 16;
    const int acbit = sub >> 1;
    const u32 rB0 = (u32)(nw * 64 + ((sub & 2) ? 8 : 0) + l7);
    const int bcbit = sub & 1;

    float acc[2][8][4];
#pragma unroll
    for (int i = 0; i < 2; i++)
#pragma unroll
        for (int j = 0; j < 8; j++)
#pragma unroll
            for (int q = 0; q < 4; q++) acc[i][j][q] = 0.f;

    auto stage = [&](int kk, u32 base) {
#pragma unroll
        for (int j = 0; j < 4; j++) {
            int r = sr + j * 32;
            u32 dst = base + (u32)(r * 128 + ((sc ^ (r & 7)) << 4));
            size_t ao = (size_t)(bm + r) * D + kk * 64 + sc * 8;
            CP16(dst,          g_xh + ao);
            CP16(dst + 16384,  g_xl + ao);
            size_t bo = (size_t)(n0 + r) * 1024 + kk * 64 + sc * 8;
            CP16(dst + 32768,  wth + bo);
            CP16(dst + 49152,  wtl + bo);
        }
    };

    // Prologue: prime 2 stages
    stage(0, sb);
    CP_COMMIT;
    stage(1, sb + G1_BUF);
    CP_COMMIT;

    for (int kk = 0; kk < 8; kk++) {
        u32 buf = sb + (u32)(kk % 3) * G1_BUF;
        if (kk < 7) {
            asm volatile("cp.async.wait_group 1;");
        } else {
            asm volatile("cp.async.wait_group 0;");
        }
        __syncthreads();
        if (kk < 6) {
            stage(kk + 2, sb + (u32)((kk + 2) % 3) * G1_BUF);
            CP_COMMIT;
        }
#pragma unroll
        for (int q = 0; q < 4; q++) {
            int ca = 2 * q + acbit;
            u32 a0[4], a1[4], al0[4], al1[4];
            u32 aoff0 = rowA0 * 128 + (u32)((ca ^ (rowA0 & 7)) << 4);
            u32 aoff1 = rowA1 * 128 + (u32)((ca ^ (rowA1 & 7)) << 4);
            ldm4(a0,  buf + aoff0);
            ldm4(a1,  buf + aoff1);
            ldm4(al0, buf + 16384 + aoff0);
            ldm4(al1, buf + 16384 + aoff1);
            int cb = 2 * q + bcbit;
#pragma unroll
            for (int j = 0; j < 4; j++) {
                u32 rB = rB0 + (u32)(j * 16);
                u32 boff = rB * 128 + (u32)((cb ^ (rB & 7)) << 4);
                u32 bh[4], bl[4];
                ldm4(bh, buf + 32768 + boff);
                ldm4(bl, buf + 49152 + boff);
                mma_bf16(acc[0][2*j],   a0,  bh[0], bh[1]);
                mma_bf16(acc[0][2*j+1], a0,  bh[2], bh[3]);
                mma_bf16(acc[1][2*j],   a1,  bh[0], bh[1]);
                mma_bf16(acc[1][2*j+1], a1,  bh[2], bh[3]);
                mma_bf16(acc[0][2*j],   al0, bh[0], bh[1]);
                mma_bf16(acc[0][2*j+1], al0, bh[2], bh[3]);
                mma_bf16(acc[1][2*j],   al1, bh[0], bh[1]);
                mma_bf16(acc[1][2*j+1], al1, bh[2], bh[3]);
                mma_bf16(acc[0][2*j],   a0,  bl[0], bl[1]);
                mma_bf16(acc[0][2*j+1], a0,  bl[2], bl[3]);
                mma_bf16(acc[1][2*j],   a1,  bl[0], bl[1]);
                mma_bf16(acc[1][2*j+1], a1,  bl[2], bl[3]);
            }
        }
    }

    float* __restrict__ Zo = dir ? g_ZB : g_ZF;
    const float* __restrict__ bias = dir ? bbw : bfw;
#pragma unroll
    for (int am = 0; am < 2; am++) {
        int m0 = bm + mw * 32 + am * 16 + gr;
#pragma unroll
        for (int p = 0; p < 8; p++) {
            int nc = n0 + nw * 64 + p * 8 + tg * 2;
            float bx = bias[nc], by = bias[nc + 1];
            const float* a = acc[am][p];
            *(float2*)(Zo + (size_t)m0 * NG + nc)       = make_float2(a[0] + bx, a[1] + by);
            *(float2*)(Zo + (size_t)(m0 + 8) * NG + nc) = make_float2(a[2] + bx, a[3] + by);
        }
    }
}

// ---------------------------------------------------------------------------
// Phase 2: unchanged from round 11 (best measured).
// ---------------------------------------------------------------------------
#define A_OFF2 0
#define B_OFF2 65536
#define SP_OFF2 (B_OFF2 + 131072)      // 2KB P handoff
#define P2_SMEM (SP_OFF2 + 2048 + 64)

__global__ void __launch_bounds__(256, 1) lstm_persistent(float* __restrict__ out)
{
    extern __shared__ char smem[];
    const u32 sb = smem_u32(smem);
    float* sP = (float*)(smem + SP_OFF2);

    const int dir   = blockIdx.x >> 6;
    const int rg    = (blockIdx.x >> 5) & 1;
    const int hTile = (blockIdx.x & 31) * 16;
    const float* __restrict__ Z = dir ? g_ZB : g_ZF;
    const __nv_bfloat16* __restrict__ wth = g_wth[dir];
    const __nv_bfloat16* __restrict__ wtl = g_wtl[dir];

    const int tid = threadIdx.x;
    const int wid = tid >> 5, lane = tid & 31;
    const int mw = wid & 1, q = wid >> 1;
    const int l7 = lane & 7, sub = lane >> 3;
    const int gr = lane >> 2, tg = lane & 3;

    const u32 aRowBase = sb + A_OFF2 + (u32)(mw * 16 + ((sub & 1) ? 8 : 0) + l7) * 2048;
    const int acbit = sub >> 1;
    const u32 bRowBase = sb + B_OFF2 + (u32)(q * 16 + ((sub & 2) ? 8 : 0) + l7) * 2048;
    const int bcbit = sub & 1;
    const int X = l7;

    // Stage B (resident)
    for (int i = tid; i < 64 * 64; i += 256) {
        int n = i >> 6, kq = i & 63;
        int q16 = n >> 4, g2 = (n >> 3) & 1, hc8 = n & 7;
        int gate = (q16 & 1) * 2 + g2;
        int hcl = (q16 >> 1) * 8 + hc8;
        size_t ng = (size_t)(gate * H + hTile + hcl) * 1024 + 512 + kq * 8;
        uint4 vh = *(const uint4*)(wth + ng);
        uint4 vl = *(const uint4*)(wtl + ng);
        u32 dst = (u32)(n * 2048 + ((kq ^ (n & 7)) << 4));
        *(uint4*)(smem + B_OFF2 + dst)        = vh;
        *(uint4*)(smem + B_OFF2 + dst + 1024) = vl;
    }
    __syncthreads();

    unsigned* bar = &g_bar2[dir][rg];
    const int R0 = mw * 16 + gr;
    const int hcl0 = (q >> 1) * 8 + tg * 2;
    const int nh = q & 1;
    const int g0 = nh * 2;
    const int hidx = (wid >> 1) * 32 + lane;  // 0..127 within mw-half
    const int halfbar = 1 + mw;
    const int pairbar = 3 + mw * 2 + (q >> 1);

    float c0x = 0.f, c0y = 0.f, c1x = 0.f, c1y = 0.f;

    for (int s = 0; s < T; s++) {
        const int t = dir ? (T - 1 - s) : s;
        const int grow = rg * 32 + R0;

        // Z prefetch BEFORE spin
        const float* zp = Z + ((size_t)t * Bsz + grow) * NG + g0 * H + hTile + hcl0;
        float2 zA0 = __ldcg((const float2*)zp);
        float2 zB0 = __ldcg((const float2*)(zp + H));
        float2 zA1 = __ldcg((const float2*)(zp + 8 * NG));
        float2 zB1 = __ldcg((const float2*)(zp + 8 * NG + H));

        if (s > 0) {
            unsigned target = 128u * (unsigned)s;
            while (ld_acquire(bar) < target) { }
        }

        // Stage A in two k-halves; pipeline second half against first mma half
        const __nv_bfloat16* hh = g_hh[s & 1][dir] + (rg * 32 + mw * 16) * H;
        const __nv_bfloat16* hl = g_hl[s & 1][dir] + (rg * 32 + mw * 16) * H;
#pragma unroll
        for (int j = 0; j < 4; j++) {                 // k-half 0: kq 0..31
            int local = hidx + j * 128;
            int r = local >> 5, kq = local & 31;
            int rfull = mw * 16 + r;
            u32 dst = sb + A_OFF2 + (u32)(rfull * 2048 + ((kq ^ (rfull & 7)) << 4));
            CP16(dst,        hh + r * 512 + kq * 8);
            CP16(dst + 1024, hl + r * 512 + kq * 8);
        }
        CP_COMMIT;
#pragma unroll
        for (int j = 0; j < 4; j++) {                 // k-half 1: kq 32..63
            int local = hidx + j * 128;
            int r = local >> 5, kq = 32 + (local & 31);
            int rfull = mw * 16 + r;
            u32 dst = sb + A_OFF2 + (u32)(rfull * 2048 + ((kq ^ (rfull & 7)) << 4));
            CP16(dst,        hh + r * 512 + kq * 8);
            CP16(dst + 1024, hl + r * 512 + kq * 8);
        }
        CP_COMMIT;
        asm volatile("cp.async.wait_group 1;");
        BAR_SYNC(halfbar, 128);

        float d0[4] = {0.f, 0.f, 0.f, 0.f}, d1[4] = {0.f, 0.f, 0.f, 0.f};
#pragma unroll 8
        for (int kt = 0; kt < 16; kt++) {
            int ca = (kt << 1) | acbit;
            int cb = (kt << 1) | bcbit;
            u32 ah[4], al[4], bh[4], bl[4];
            ldm4(ah, aRowBase + (u32)((ca ^ X) << 4));
            ldm4(al, aRowBase + (u32)(((ca + 64) ^ X) << 4));
            ldm4(bh, bRowBase + (u32)((cb ^ X) << 4));
            ldm4(bl, bRowBase + (u32)(((cb + 64) ^ X) << 4));
            mma_bf16(d0, ah, bh[0], bh[1]);
            mma_bf16(d1, ah, bh[2], bh[3]);
            mma_bf16(d0, al, bh[0], bh[1]);
            mma_bf16(d1, al, bh[2], bh[3]);
            mma_bf16(d0, ah, bl[0], bl[1]);
            mma_bf16(d1, ah, bl[2], bl[3]);
        }
        asm volatile("cp.async.wait_group 0;");
        BAR_SYNC(halfbar, 128);
#pragma unroll 8
        for (int kt = 16; kt < 32; kt++) {
            int ca = (kt << 1) | acbit;
            int cb = (kt << 1) | bcbit;
            u32 ah[4], al[4], bh[4], bl[4];
            ldm4(ah, aRowBase + (u32)((ca ^ X) << 4));
            ldm4(al, aRowBase + (u32)(((ca + 64) ^ X) << 4));
            ldm4(bh, bRowBase + (u32)((cb ^ X) << 4));
            ldm4(bl, bRowBase + (u32)(((cb + 64) ^ X) << 4));
            mma_bf16(d0, ah, bh[0], bh[1]);
            mma_bf16(d1, ah, bh[2], bh[3]);
            mma_bf16(d0, al, bh[0], bh[1]);
            mma_bf16(d1, al, bh[2], bh[3]);
            mma_bf16(d0, ah, bl[0], bl[1]);
            mma_bf16(d1, ah, bl[2], bl[3]);
        }

        // Epilogue
        if (nh == 0) {
            float2 p0, p1;
            p0.x = sigf(d0[0] + zA0.x) * tanh_fast(d1[0] + zB0.x);
            p0.y = sigf(d0[1] + zA0.y) * tanh_fast(d1[1] + zB0.y);
            p1.x = sigf(d0[2] + zA1.x) * tanh_fast(d1[2] + zB1.x);
            p1.y = sigf(d0[3] + zA1.y) * tanh_fast(d1[3] + zB1.y);
            *(float2*)&sP[R0 * 16 + hcl0]       = p0;
            *(float2*)&sP[(R0 + 8) * 16 + hcl0] = p1;
            BAR_SYNC(pairbar, 64);
        } else {
            float Fv[4], Ov[4];
            Fv[0] = sigf(d0[0] + zA0.x + 1.f); Fv[1] = sigf(d0[1] + zA0.y + 1.f);
            Fv[2] = sigf(d0[2] + zA1.x + 1.f); Fv[3] = sigf(d0[3] + zA1.y + 1.f);
            Ov[0] = sigf(d1[0] + zB0.x); Ov[1] = sigf(d1[1] + zB0.y);
            Ov[2] = sigf(d1[2] + zB1.x); Ov[3] = sigf(d1[3] + zB1.y);
            BAR_SYNC(pairbar, 64);

            float2 P0 = *(const float2*)&sP[R0 * 16 + hcl0];
            float2 P1 = *(const float2*)&sP[(R0 + 8) * 16 + hcl0];
            c0x = Fv[0] * c0x + P0.x; c0y = Fv[1] * c0y + P0.y;
            c1x = Fv[2] * c1x + P1.x; c1y = Fv[3] * c1y + P1.y;
            float h0x = Ov[0] * tanh_fast(c0x), h0y = Ov[1] * tanh_fast(c0y);
            float h1x = Ov[2] * tanh_fast(c1x), h1y = Ov[3] * tanh_fast(c1y);

            u16 ha0, la0, ha1, la1, hb0, lb0, hb1, lb1;
            split_bf16(h0x, ha0, la0); split_bf16(h0y, ha1, la1);
            split_bf16(h1x, hb0, lb0); split_bf16(h1y, hb1, lb1);
            int pp = (s & 1) ^ 1;
            u32 o0 = (u32)(grow * H + hTile + hcl0);
            u32 o1 = o0 + 8 * H;
            *(u32*)&g_hh[pp][dir][o0] = (u32)ha0 | ((u32)ha1 << 16);
            *(u32*)&g_hl[pp][dir][o0] = (u32)la0 | ((u32)la1 << 16);
            *(u32*)&g_hh[pp][dir][o1] = (u32)hb0 | ((u32)hb1 << 16);
            *(u32*)&g_hl[pp][dir][o1] = (u32)lb0 | ((u32)lb1 << 16);

            __syncwarp();
            if (lane == 0) red_release_add(bar, 1u);

            *(float2*)(out + ((size_t)grow * T + t) * (2 * H) + dir * H + hTile + hcl0)
                = make_float2(h0x, h0y);
            *(float2*)(out + ((size_t)(grow + 8) * T + t) * (2 * H) + dir * H + hTile + hcl0)
                = make_float2(h1x, h1y);
        }
    }
}

extern "C" void kernel_launch(void* const* d_in, const int* in_sizes, int n_in,
                              void* d_out, int out_size) {
    const float* x    = (const float*)d_in[0];
    const float* W_fw = (const float*)d_in[1];
    const float* b_fw = (const float*)d_in[2];
    const float* W_bw = (const float*)d_in[3];
    const float* b_bw = (const float*)d_in[4];
    float* out = (float*)d_out;

    (void)in_sizes; (void)n_in; (void)out_size;

    cudaFuncSetAttribute(gemm_x_mma,
                         cudaFuncAttributeMaxDynamicSharedMemorySize, G1_SMEM);
    cudaFuncSetAttribute(lstm_persistent,
                         cudaFuncAttributeMaxDynamicSharedMemorySize, P2_SMEM);

    init_kernel<<<(Bsz * H + 255) / 256, 256>>>();
    split_x_kernel<<<MTOT * 64 / 256, 256>>>(x);
    split_w_kernel<<<dim3(32, 64, 2), 256>>>(W_fw, W_bw);

    gemm_x_mma<<<dim3(32, 256), 256, G1_SMEM>>>(b_fw, b_bw);

    lstm_persistent<<<128, 256, P2_SMEM>>>(out);
}

// round 13
// speedup vs baseline: 1.3690x; 1.0198x over previous
#include <cuda_runtime.h>
#include <cuda_bf16.h>
#include <math.h>

#define Bsz 64
#define T 512
#define D 512
#define H 512
#define NG 2048  // 4*H
#define MTOT (Bsz*T)  // 32768

typedef unsigned long long u64;
typedef unsigned int u32;
typedef unsigned short u16;

// ---- common helpers ----
__device__ __forceinline__ u32 smem_u32(const void* p) {
    u32 a;
    asm("{ .reg .u64 t; cvta.to.shared.u64 t, %1; cvt.u32.u64 %0, t; }" : "=r"(a) : "l"(p));
    return a;
}
__device__ __forceinline__ void ldm4(u32* r, u32 p) {
    asm volatile("ldmatrix.sync.aligned.m8n8.x4.shared.b16 {%0,%1,%2,%3}, [%4];"
        : "=r"(r[0]), "=r"(r[1]), "=r"(r[2]), "=r"(r[3]) : "r"(p));
}
__device__ __forceinline__ void mma_bf16(float* d, const u32* a, u32 b0, u32 b1) {
    asm volatile("mma.sync.aligned.m16n8k16.row.col.f32.bf16.bf16.f32 "
        "{%0,%1,%2,%3}, {%4,%5,%6,%7}, {%8,%9}, {%0,%1,%2,%3};"
        : "+f"(d[0]), "+f"(d[1]), "+f"(d[2]), "+f"(d[3])
        : "r"(a[0]), "r"(a[1]), "r"(a[2]), "r"(a[3]), "r"(b0), "r"(b1));
}
__device__ __forceinline__ void split_bf16(float x, u16& hb, u16& lb) {
    __nv_bfloat16 h = __float2bfloat16_rn(x);
    hb = __bfloat16_as_ushort(h);
    lb = __bfloat16_as_ushort(__float2bfloat16_rn(x - __bfloat162float(h)));
}
__device__ __forceinline__ float sigf(float x) {
    float e, r;
    asm("ex2.approx.f32 %0, %1;" : "=f"(e) : "f"(-x * 1.4426950408889634f));
    asm("rcp.approx.f32 %0, %1;" : "=f"(r) : "f"(1.0f + e));
    return r;
}
__device__ __forceinline__ float tanh_fast(float x) {
    return fmaf(2.f, sigf(2.f * x), -1.f);
}
__device__ __forceinline__ void red_release_add(unsigned* p, unsigned v) {
    asm volatile("red.release.gpu.global.add.u32 [%0], %1;" :: "l"(p), "r"(v) : "memory");
}
__device__ __forceinline__ unsigned ld_acquire(const unsigned* p) {
    unsigned v;
    asm volatile("ld.acquire.gpu.global.u32 %0, [%1];" : "=r"(v) : "l"(p) : "memory");
    return v;
}
#define CP16(dst, src) \
    asm volatile("cp.async.cg.shared.global [%0], [%1], 16;" :: "r"(dst), "l"(src))
#define CP_COMMIT asm volatile("cp.async.commit_group;")
#define BAR_SYNC(id, cnt) asm volatile("bar.sync %0, %1;" :: "r"(id), "r"(cnt) : "memory")

// ---- scratch ----
__device__ float g_ZF[(size_t)T * Bsz * NG];
__device__ float g_ZB[(size_t)T * Bsz * NG];
__device__ __align__(16) __nv_bfloat16 g_hh[2][2][Bsz * H];
__device__ __align__(16) __nv_bfloat16 g_hl[2][2][Bsz * H];
__device__ __align__(16) __nv_bfloat16 g_xh[(size_t)MTOT * D];   // row m = t*B + b
__device__ __align__(16) __nv_bfloat16 g_xl[(size_t)MTOT * D];
__device__ __align__(16) __nv_bfloat16 g_wth[2][(size_t)NG * 1024]; // [dir][n][k]
__device__ __align__(16) __nv_bfloat16 g_wtl[2][(size_t)NG * 1024];
__device__ unsigned g_bar2[2][2];      // [dir][rg]

__global__ void init_kernel() {
    int i = blockIdx.x * blockDim.x + threadIdx.x;
    if (i < Bsz * H) {
        __nv_bfloat16 z = __float2bfloat16(0.f);
        g_hh[0][0][i] = z; g_hh[0][1][i] = z; g_hh[1][0][i] = z; g_hh[1][1][i] = z;
        g_hl[0][0][i] = z; g_hl[0][1][i] = z; g_hl[1][0][i] = z; g_hl[1][1][i] = z;
    }
    if (i < 2) { g_bar2[i][0] = 0u; g_bar2[i][1] = 0u; }
}

__global__ void __launch_bounds__(256) split_x_kernel(const float* __restrict__ x) {
    int id = blockIdx.x * 256 + threadIdx.x;
    int m = id >> 6, c8 = id & 63;
    int b = m & (Bsz - 1), t = m >> 6;
    const float4* xp = (const float4*)(x + ((size_t)b * T + t) * D + c8 * 8);
    float4 v0 = xp[0], v1 = xp[1];
    u16 h[8], l[8];
    split_bf16(v0.x, h[0], l[0]); split_bf16(v0.y, h[1], l[1]);
    split_bf16(v0.z, h[2], l[2]); split_bf16(v0.w, h[3], l[3]);
    split_bf16(v1.x, h[4], l[4]); split_bf16(v1.y, h[5], l[5]);
    split_bf16(v1.z, h[6], l[6]); split_bf16(v1.w, h[7], l[7]);
    uint4 ph, pl;
    ph.x = (u32)h[0] | ((u32)h[1] << 16); ph.y = (u32)h[2] | ((u32)h[3] << 16);
    ph.z = (u32)h[4] | ((u32)h[5] << 16); ph.w = (u32)h[6] | ((u32)h[7] << 16);
    pl.x = (u32)l[0] | ((u32)l[1] << 16); pl.y = (u32)l[2] | ((u32)l[3] << 16);
    pl.z = (u32)l[4] | ((u32)l[5] << 16); pl.w = (u32)l[6] | ((u32)l[7] << 16);
    *(uint4*)(g_xh + (size_t)m * D + c8 * 8) = ph;
    *(uint4*)(g_xl + (size_t)m * D + c8 * 8) = pl;
}

__global__ void __launch_bounds__(256) split_w_kernel(
    const float* __restrict__ Wfw, const float* __restrict__ Wbw) {
    __shared__ float tile[32][33];
    int dir = blockIdx.z;
    int k0 = blockIdx.x * 32, n0 = blockIdx.y * 32;
    const float* W = dir ? Wbw : Wfw;
    int tid = threadIdx.x;
#pragma unroll
    for (int i = 0; i < 4; i++) {
        int idx = tid + i * 256;
        int r = idx >> 5, c = idx & 31;
        tile[r][c] = W[(size_t)(k0 + r) * NG + n0 + c];
    }
    __syncthreads();
#pragma unroll
    for (int i = 0; i < 4; i++) {
        int idx = tid + i * 256;
        int r = idx >> 5, c = idx & 31;
        u16 hb, lb; split_bf16(tile[c][r], hb, lb);
        size_t o = (size_t)(n0 + r) * 1024 + k0 + c;
        g_wth[dir][o] = __ushort_as_bfloat16(hb);
        g_wtl[dir][o] = __ushort_as_bfloat16(lb);
    }
}

// ---------------------------------------------------------------------------
// Phase 1: 3-stage cp.async pipeline (unchanged from R12).
// ---------------------------------------------------------------------------
#define G1_BUF 65536
#define G1_SMEM (3 * G1_BUF)

__global__ void __launch_bounds__(256, 1) gemm_x_mma(
    const float* __restrict__ bfw, const float* __restrict__ bbw)
{
    extern __shared__ char smem[];
    const u32 sb = smem_u32(smem);
    const int tid = threadIdx.x;
    const int wid = tid >> 5, lane = tid & 31;
    const int mw = wid & 3, nw = wid >> 2;
    const int l7 = lane & 7, sub = lane >> 3, gr = lane >> 2, tg = lane & 3;

    const int bm = blockIdx.y * 128;
    const int bn = blockIdx.x * 128;
    const int dir = bn >= 2048;
    const int n0 = bn - dir * 2048;
    const __nv_bfloat16* __restrict__ wth = g_wth[dir];
    const __nv_bfloat16* __restrict__ wtl = g_wtl[dir];

    const int sr = tid >> 3;
    const int sc = tid & 7;

    const u32 rowA0 = (u32)(mw * 32 + (sub & 1) * 8 + l7);
    const u32 rowA1 = rowA0 + 16;
    const int acbit = sub >> 1;
    const u32 rB0 = (u32)(nw * 64 + ((sub & 2) ? 8 : 0) + l7);
    const int bcbit = sub & 1;

    float acc[2][8][4];
#pragma unroll
    for (int i = 0; i < 2; i++)
#pragma unroll
        for (int j = 0; j < 8; j++)
#pragma unroll
            for (int q = 0; q < 4; q++) acc[i][j][q] = 0.f;

    auto stage = [&](int kk, u32 base) {
#pragma unroll
        for (int j = 0; j < 4; j++) {
            int r = sr + j * 32;
            u32 dst = base + (u32)(r * 128 + ((sc ^ (r & 7)) << 4));
            size_t ao = (size_t)(bm + r) * D + kk * 64 + sc * 8;
            CP16(dst,          g_xh + ao);
            CP16(dst + 16384,  g_xl + ao);
            size_t bo = (size_t)(n0 + r) * 1024 + kk * 64 + sc * 8;
            CP16(dst + 32768,  wth + bo);
            CP16(dst + 49152,  wtl + bo);
        }
    };

    stage(0, sb);
    CP_COMMIT;
    stage(1, sb + G1_BUF);
    CP_COMMIT;

    for (int kk = 0; kk < 8; kk++) {
        u32 buf = sb + (u32)(kk % 3) * G1_BUF;
        if (kk < 7) {
            asm volatile("cp.async.wait_group 1;");
        } else {
            asm volatile("cp.async.wait_group 0;");
        }
        __syncthreads();
        if (kk < 6) {
            stage(kk + 2, sb + (u32)((kk + 2) % 3) * G1_BUF);
            CP_COMMIT;
        }
#pragma unroll
        for (int q = 0; q < 4; q++) {
            int ca = 2 * q + acbit;
            u32 a0[4], a1[4], al0[4], al1[4];
            u32 aoff0 = rowA0 * 128 + (u32)((ca ^ (rowA0 & 7)) << 4);
            u32 aoff1 = rowA1 * 128 + (u32)((ca ^ (rowA1 & 7)) << 4);
            ldm4(a0,  buf + aoff0);
            ldm4(a1,  buf + aoff1);
            ldm4(al0, buf + 16384 + aoff0);
            ldm4(al1, buf + 16384 + aoff1);
            int cb = 2 * q + bcbit;
#pragma unroll
            for (int j = 0; j < 4; j++) {
                u32 rB = rB0 + (u32)(j * 16);
                u32 boff = rB * 128 + (u32)((cb ^ (rB & 7)) << 4);
                u32 bh[4], bl[4];
                ldm4(bh, buf + 32768 + boff);
                ldm4(bl, buf + 49152 + boff);
                mma_bf16(acc[0][2*j],   a0,  bh[0], bh[1]);
                mma_bf16(acc[0][2*j+1], a0,  bh[2], bh[3]);
                mma_bf16(acc[1][2*j],   a1,  bh[0], bh[1]);
                mma_bf16(acc[1][2*j+1], a1,  bh[2], bh[3]);
                mma_bf16(acc[0][2*j],   al0, bh[0], bh[1]);
                mma_bf16(acc[0][2*j+1], al0, bh[2], bh[3]);
                mma_bf16(acc[1][2*j],   al1, bh[0], bh[1]);
                mma_bf16(acc[1][2*j+1], al1, bh[2], bh[3]);
                mma_bf16(acc[0][2*j],   a0,  bl[0], bl[1]);
                mma_bf16(acc[0][2*j+1], a0,  bl[2], bl[3]);
                mma_bf16(acc[1][2*j],   a1,  bl[0], bl[1]);
                mma_bf16(acc[1][2*j+1], a1,  bl[2], bl[3]);
            }
        }
    }

    float* __restrict__ Zo = dir ? g_ZB : g_ZF;
    const float* __restrict__ bias = dir ? bbw : bfw;
#pragma unroll
    for (int am = 0; am < 2; am++) {
        int m0 = bm + mw * 32 + am * 16 + gr;
#pragma unroll
        for (int p = 0; p < 8; p++) {
            int nc = n0 + nw * 64 + p * 8 + tg * 2;
            float bx = bias[nc], by = bias[nc + 1];
            const float* a = acc[am][p];
            *(float2*)(Zo + (size_t)m0 * NG + nc)       = make_float2(a[0] + bx, a[1] + by);
            *(float2*)(Zo + (size_t)(m0 + 8) * NG + nc) = make_float2(a[2] + bx, a[3] + by);
        }
    }
}

// ---------------------------------------------------------------------------
// Phase 2 v6: per-term accumulators (6 chains/warp) to break the HMMA
// dependency chain; epilogue sums the three terms. Otherwise identical to R12.
// ---------------------------------------------------------------------------
#define A_OFF2 0
#define B_OFF2 65536
#define SP_OFF2 (B_OFF2 + 131072)      // 2KB P handoff
#define P2_SMEM (SP_OFF2 + 2048 + 64)

__global__ void __launch_bounds__(256, 1) lstm_persistent(float* __restrict__ out)
{
    extern __shared__ char smem[];
    const u32 sb = smem_u32(smem);
    float* sP = (float*)(smem + SP_OFF2);

    const int dir   = blockIdx.x >> 6;
    const int rg    = (blockIdx.x >> 5) & 1;
    const int hTile = (blockIdx.x & 31) * 16;
    const float* __restrict__ Z = dir ? g_ZB : g_ZF;
    const __nv_bfloat16* __restrict__ wth = g_wth[dir];
    const __nv_bfloat16* __restrict__ wtl = g_wtl[dir];

    const int tid = threadIdx.x;
    const int wid = tid >> 5, lane = tid & 31;
    const int mw = wid & 1, q = wid >> 1;
    const int l7 = lane & 7, sub = lane >> 3;
    const int gr = lane >> 2, tg = lane & 3;

    const u32 aRowBase = sb + A_OFF2 + (u32)(mw * 16 + ((sub & 1) ? 8 : 0) + l7) * 2048;
    const int acbit = sub >> 1;
    const u32 bRowBase = sb + B_OFF2 + (u32)(q * 16 + ((sub & 2) ? 8 : 0) + l7) * 2048;
    const int bcbit = sub & 1;
    const int X = l7;

    // Stage B (resident)
    for (int i = tid; i < 64 * 64; i += 256) {
        int n = i >> 6, kq = i & 63;
        int q16 = n >> 4, g2 = (n >> 3) & 1, hc8 = n & 7;
        int gate = (q16 & 1) * 2 + g2;
        int hcl = (q16 >> 1) * 8 + hc8;
        size_t ng = (size_t)(gate * H + hTile + hcl) * 1024 + 512 + kq * 8;
        uint4 vh = *(const uint4*)(wth + ng);
        uint4 vl = *(const uint4*)(wtl + ng);
        u32 dst = (u32)(n * 2048 + ((kq ^ (n & 7)) << 4));
        *(uint4*)(smem + B_OFF2 + dst)        = vh;
        *(uint4*)(smem + B_OFF2 + dst + 1024) = vl;
    }
    __syncthreads();

    unsigned* bar = &g_bar2[dir][rg];
    const int R0 = mw * 16 + gr;
    const int hcl0 = (q >> 1) * 8 + tg * 2;
    const int nh = q & 1;
    const int g0 = nh * 2;
    const int hidx = (wid >> 1) * 32 + lane;  // 0..127 within mw-half
    const int halfbar = 1 + mw;
    const int pairbar = 3 + mw * 2 + (q >> 1);

    float c0x = 0.f, c0y = 0.f, c1x = 0.f, c1y = 0.f;

    for (int s = 0; s < T; s++) {
        const int t = dir ? (T - 1 - s) : s;
        const int grow = rg * 32 + R0;

        // Z prefetch BEFORE spin
        const float* zp = Z + ((size_t)t * Bsz + grow) * NG + g0 * H + hTile + hcl0;
        float2 zA0 = __ldcg((const float2*)zp);
        float2 zB0 = __ldcg((const float2*)(zp + H));
        float2 zA1 = __ldcg((const float2*)(zp + 8 * NG));
        float2 zB1 = __ldcg((const float2*)(zp + 8 * NG + H));

        if (s > 0) {
            unsigned target = 128u * (unsigned)s;
            while (ld_acquire(bar) < target) { }
        }

        // Stage A in two k-halves; pipeline second half against first mma half
        const __nv_bfloat16* hh = g_hh[s & 1][dir] + (rg * 32 + mw * 16) * H;
        const __nv_bfloat16* hl = g_hl[s & 1][dir] + (rg * 32 + mw * 16) * H;
#pragma unroll
        for (int j = 0; j < 4; j++) {                 // k-half 0: kq 0..31
            int local = hidx + j * 128;
            int r = local >> 5, kq = local & 31;
            int rfull = mw * 16 + r;
            u32 dst = sb + A_OFF2 + (u32)(rfull * 2048 + ((kq ^ (rfull & 7)) << 4));
            CP16(dst,        hh + r * 512 + kq * 8);
            CP16(dst + 1024, hl + r * 512 + kq * 8);
        }
        CP_COMMIT;
#pragma unroll
        for (int j = 0; j < 4; j++) {                 // k-half 1: kq 32..63
            int local = hidx + j * 128;
            int r = local >> 5, kq = 32 + (local & 31);
            int rfull = mw * 16 + r;
            u32 dst = sb + A_OFF2 + (u32)(rfull * 2048 + ((kq ^ (rfull & 7)) << 4));
            CP16(dst,        hh + r * 512 + kq * 8);
            CP16(dst + 1024, hl + r * 512 + kq * 8);
        }
        CP_COMMIT;
        asm volatile("cp.async.wait_group 1;");
        BAR_SYNC(halfbar, 128);

        // Per-term accumulators: 6 independent HMMA chains per warp
        float d0h[4] = {0.f,0.f,0.f,0.f}, d1h[4] = {0.f,0.f,0.f,0.f};
        float d0a[4] = {0.f,0.f,0.f,0.f}, d1a[4] = {0.f,0.f,0.f,0.f};
        float d0b[4] = {0.f,0.f,0.f,0.f}, d1b[4] = {0.f,0.f,0.f,0.f};
#pragma unroll 8
        for (int kt = 0; kt < 16; kt++) {
            int ca = (kt << 1) | acbit;
            int cb = (kt << 1) | bcbit;
            u32 ah[4], al[4], bh[4], bl[4];
            ldm4(ah, aRowBase + (u32)((ca ^ X) << 4));
            ldm4(al, aRowBase + (u32)(((ca + 64) ^ X) << 4));
            ldm4(bh, bRowBase + (u32)((cb ^ X) << 4));
            ldm4(bl, bRowBase + (u32)(((cb + 64) ^ X) << 4));
            mma_bf16(d0h, ah, bh[0], bh[1]);
            mma_bf16(d1h, ah, bh[2], bh[3]);
            mma_bf16(d0a, al, bh[0], bh[1]);
            mma_bf16(d1a, al, bh[2], bh[3]);
            mma_bf16(d0b, ah, bl[0], bl[1]);
            mma_bf16(d1b, ah, bl[2], bl[3]);
        }
        asm volatile("cp.async.wait_group 0;");
        BAR_SYNC(halfbar, 128);
#pragma unroll 8
        for (int kt = 16; kt < 32; kt++) {
            int ca = (kt << 1) | acbit;
            int cb = (kt << 1) | bcbit;
            u32 ah[4], al[4], bh[4], bl[4];
            ldm4(ah, aRowBase + (u32)((ca ^ X) << 4));
            ldm4(al, aRowBase + (u32)(((ca + 64) ^ X) << 4));
            ldm4(bh, bRowBase + (u32)((cb ^ X) << 4));
            ldm4(bl, bRowBase + (u32)(((cb + 64) ^ X) << 4));
            mma_bf16(d0h, ah, bh[0], bh[1]);
            mma_bf16(d1h, ah, bh[2], bh[3]);
            mma_bf16(d0a, al, bh[0], bh[1]);
            mma_bf16(d1a, al, bh[2], bh[3]);
            mma_bf16(d0b, ah, bl[0], bl[1]);
            mma_bf16(d1b, ah, bl[2], bl[3]);
        }

        float d0[4], d1[4];
#pragma unroll
        for (int e = 0; e < 4; e++) {
            d0[e] = d0h[e] + d0a[e] + d0b[e];
            d1[e] = d1h[e] + d1a[e] + d1b[e];
        }

        // Epilogue
        if (nh == 0) {
            float2 p0, p1;
            p0.x = sigf(d0[0] + zA0.x) * tanh_fast(d1[0] + zB0.x);
            p0.y = sigf(d0[1] + zA0.y) * tanh_fast(d1[1] + zB0.y);
            p1.x = sigf(d0[2] + zA1.x) * tanh_fast(d1[2] + zB1.x);
            p1.y = sigf(d0[3] + zA1.y) * tanh_fast(d1[3] + zB1.y);
            *(float2*)&sP[R0 * 16 + hcl0]       = p0;
            *(float2*)&sP[(R0 + 8) * 16 + hcl0] = p1;
            BAR_SYNC(pairbar, 64);
        } else {
            float Fv[4], Ov[4];
            Fv[0] = sigf(d0[0] + zA0.x + 1.f); Fv[1] = sigf(d0[1] + zA0.y + 1.f);
            Fv[2] = sigf(d0[2] + zA1.x + 1.f); Fv[3] = sigf(d0[3] + zA1.y + 1.f);
            Ov[0] = sigf(d1[0] + zB0.x); Ov[1] = sigf(d1[1] + zB0.y);
            Ov[2] = sigf(d1[2] + zB1.x); Ov[3] = sigf(d1[3] + zB1.y);
            BAR_SYNC(pairbar, 64);

            float2 P0 = *(const float2*)&sP[R0 * 16 + hcl0];
            float2 P1 = *(const float2*)&sP[(R0 + 8) * 16 + hcl0];
            c0x = Fv[0] * c0x + P0.x; c0y = Fv[1] * c0y + P0.y;
            c1x = Fv[2] * c1x + P1.x; c1y = Fv[3] * c1y + P1.y;
            float h0x = Ov[0] * tanh_fast(c0x), h0y = Ov[1] * tanh_fast(c0y);
            float h1x = Ov[2] * tanh_fast(c1x), h1y = Ov[3] * tanh_fast(c1y);

            u16 ha0, la0, ha1, la1, hb0, lb0, hb1, lb1;
            split_bf16(h0x, ha0, la0); split_bf16(h0y, ha1, la1);
            split_bf16(h1x, hb0, lb0); split_bf16(h1y, hb1, lb1);
            int pp = (s & 1) ^ 1;
            u32 o0 = (u32)(grow * H + hTile + hcl0);
            u32 o1 = o0 + 8 * H;
            *(u32*)&g_hh[pp][dir][o0] = (u32)ha0 | ((u32)ha1 << 16);
            *(u32*)&g_hl[pp][dir][o0] = (u32)la0 | ((u32)la1 << 16);
            *(u32*)&g_hh[pp][dir][o1] = (u32)hb0 | ((u32)hb1 << 16);
            *(u32*)&g_hl[pp][dir][o1] = (u32)lb0 | ((u32)lb1 << 16);

            __syncwarp();
            if (lane == 0) red_release_add(bar, 1u);

            *(float2*)(out + ((size_t)grow * T + t) * (2 * H) + dir * H + hTile + hcl0)
                = make_float2(h0x, h0y);
            *(float2*)(out + ((size_t)(grow + 8) * T + t) * (2 * H) + dir * H + hTile + hcl0)
                = make_float2(h1x, h1y);
        }
    }
}

extern "C" void kernel_launch(void* const* d_in, const int* in_sizes, int n_in,
                              void* d_out, int out_size) {
    const float* x    = (const float*)d_in[0];
    const float* W_fw = (const float*)d_in[1];
    const float* b_fw = (const float*)d_in[2];
    const float* W_bw = (const float*)d_in[3];
    const float* b_bw = (const float*)d_in[4];
    float* out = (float*)d_out;

    (void)in_sizes; (void)n_in; (void)out_size;

    cudaFuncSetAttribute(gemm_x_mma,
                         cudaFuncAttributeMaxDynamicSharedMemorySize, G1_SMEM);
    cudaFuncSetAttribute(lstm_persistent,
                         cudaFuncAttributeMaxDynamicSharedMemorySize, P2_SMEM);

    init_kernel<<<(Bsz * H + 255) / 256, 256>>>();
    split_x_kernel<<<MTOT * 64 / 256, 256>>>(x);
    split_w_kernel<<<dim3(32, 64, 2), 256>>>(W_fw, W_bw);

    gemm_x_mma<<<dim3(32, 256), 256, G1_SMEM>>>(b_fw, b_bw);

    lstm_persistent<<<128, 256, P2_SMEM>>>(out);
}